// round 15
// baseline (speedup 1.0000x reference)
#include <cuda_runtime.h>
#include <cuda_bf16.h>
#include <math.h>

#define NN 100000
#define NE 800000
#define NG 16
#define NF 128
#define NH 128
#define NC 2

#define GB 782            // gemm blocks in k_gemmfill
#define FB 3125           // fill blocks
#define HB 3125           // hist blocks

typedef unsigned long long ull;

// ---------------- persistent scratch (alloc-free rule: __device__ globals) ---
__device__ int            g_deg[NN];
__device__ float          g_dinv[NN];
__device__ int            g_ptr[NN + 1];
__device__ int            g_fill[NN];
__device__ int            g_srcs[NE];
__device__ __nv_bfloat16  g_h1b[(size_t)NN * NF];  // bf16(dinv * (x @ W1))
__device__ float          g_h2[NN * NC];           // dinv * (act @ W2)
__device__ float          g_sums[NG * NC];
__device__ float          g_cnts[NG];
__device__ int            g_bsum[32];
__device__ float4         g_wfragh[2048];          // W1 bf16 m16n8k16 fragments

// ---------------- helpers -------------------------------------------------
__device__ __forceinline__ void mma_bf16(float& c0, float& c1, float& c2, float& c3,
                                         unsigned a0, unsigned a1, unsigned a2, unsigned a3,
                                         unsigned b0, unsigned b1) {
    asm("mma.sync.aligned.m16n8k16.row.col.f32.bf16.bf16.f32 "
        "{%0,%1,%2,%3}, {%4,%5,%6,%7}, {%8,%9}, {%0,%1,%2,%3};"
        : "+f"(c0), "+f"(c1), "+f"(c2), "+f"(c3)
        : "r"(a0), "r"(a1), "r"(a2), "r"(a3), "r"(b0), "r"(b1));
}

__device__ __forceinline__ unsigned bf2u(float a, float b) {
    __nv_bfloat162 h = __floats2bfloat162_rn(a, b);
    return *reinterpret_cast<unsigned*>(&h);
}

__device__ __forceinline__ void cpa16(unsigned dst, const void* src, int srcsz) {
    asm volatile("cp.async.cg.shared.global [%0], [%1], 16, %2;"
                 :: "r"(dst), "l"(src), "r"(srcsz));
}
__device__ __forceinline__ void cpa_commit() {
    asm volatile("cp.async.commit_group;");
}
template <int N>
__device__ __forceinline__ void cpa_wait() {
    asm volatile("cp.async.wait_group %0;" :: "n"(N));
}

// bf16x2 word -> packed f32x2 (exact: bf16 bits << 16 == f32 bits)
__device__ __forceinline__ ull bfpair(unsigned raw) {
    unsigned lo, hi; ull p;
    asm("shl.b32 %0, %1, 16;" : "=r"(lo) : "r"(raw));
    asm("and.b32 %0, %1, 0xFFFF0000;" : "=r"(hi) : "r"(raw));
    asm("mov.b64 %0, {%1, %2};" : "=l"(p) : "r"(lo), "r"(hi));
    return p;
}
__device__ __forceinline__ void addf2(ull& acc, ull v) {
    asm("add.rn.f32x2 %0, %0, %1;" : "+l"(acc) : "l"(v));
}
__device__ __forceinline__ float2 unpk(ull p) {
    float2 f;
    asm("mov.b64 {%0, %1}, %2;" : "=f"(f.x), "=f"(f.y) : "l"(p));
    return f;
}

// ---------- launch 1: degree histogram  ||  W1 bf16 fragment transform ----
__global__ void k_histinit(const int* __restrict__ ei, const float* __restrict__ W) {
    int b = blockIdx.x;
    if (b < HB) {
        int e = b * 256 + threadIdx.x;
        if (e < NE) atomicAdd(&g_deg[ei[NE + e]], 1);
    } else {
        int i = (b - HB) * 256 + threadIdx.x;       // 0..2047
        int lane = i & 31, ntp = (i >> 5) & 7, sg = i >> 8;
        int g = lane >> 2, tig = lane & 3;
        int k0 = sg * 16;
        int n0 = ntp * 16 + g, n1 = n0 + 8;
        float4 f;
        f.x = __uint_as_float(bf2u(W[(k0 + 2*tig    ) * 128 + n0], W[(k0 + 2*tig + 1) * 128 + n0]));
        f.y = __uint_as_float(bf2u(W[(k0 + 2*tig + 8) * 128 + n0], W[(k0 + 2*tig + 9) * 128 + n0]));
        f.z = __uint_as_float(bf2u(W[(k0 + 2*tig    ) * 128 + n1], W[(k0 + 2*tig + 1) * 128 + n1]));
        f.w = __uint_as_float(bf2u(W[(k0 + 2*tig + 8) * 128 + n1], W[(k0 + 2*tig + 9) * 128 + n1]));
        g_wfragh[i] = f;
    }
}

// ---------- launch 2: block-parallel scan of deg -> ptr (+dinv) -----------
__global__ void k_scanA() {
    __shared__ int wsum[32];
    int b = blockIdx.x, t = threadIdx.x;
    int lane = t & 31, wid = t >> 5;
    int base = b * 4096 + t * 4;
    int v[4]; int s = 0;
#pragma unroll
    for (int j = 0; j < 4; ++j) {
        v[j] = (base + j < NN) ? g_deg[base + j] : 0;
        s += v[j];
    }
#pragma unroll
    for (int j = 0; j < 4; ++j)
        if (base + j < NN) g_dinv[base + j] = rsqrtf((float)(v[j] + 1));
    int inc = s;
#pragma unroll
    for (int off = 1; off < 32; off <<= 1) {
        int n = __shfl_up_sync(0xffffffffu, inc, off);
        if (lane >= off) inc += n;
    }
    if (lane == 31) wsum[wid] = inc;
    __syncthreads();
    if (wid == 0) {
        int w = wsum[lane];
        int wi = w;
#pragma unroll
        for (int off = 1; off < 32; off <<= 1) {
            int n = __shfl_up_sync(0xffffffffu, wi, off);
            if (lane >= off) wi += n;
        }
        wsum[lane] = wi - w;
    }
    __syncthreads();
    int excl = inc - s + wsum[wid];
    if (t == 1023) g_bsum[b] = inc + wsum[31];
    int run = excl;
#pragma unroll
    for (int j = 0; j < 4; ++j) {
        if (base + j < NN) g_ptr[base + j] = run;
        run += v[j];
    }
}

// ---------- launch 3: spine scan folded into the add pass -----------------
__global__ void k_spineAdd() {
    __shared__ int off[32];
    int t = threadIdx.x;
    if (t < 32) {
        int v = (t < 25) ? g_bsum[t] : 0;
        int inc = v;
#pragma unroll
        for (int o = 1; o < 32; o <<= 1) {
            int n = __shfl_up_sync(0xffffffffu, inc, o);
            if (t >= o) inc += n;
        }
        off[t] = inc - v;
    }
    __syncthreads();
    int i = blockIdx.x * 1024 + t;
    if (i < NN) g_ptr[i] += off[i >> 12];
    if (i == 0) g_ptr[NN] = NE;
}

// ---------- launch 4 (ncu slot): bf16 MMA GEMM1 with INTERLEAVED fill -----
// bid % 5 == 0 -> gemm block bid/5 (782); else fill block bid - bid/5 - 1
// (3125). Fill's memory/atomic work issues into the gemm's latency bubbles.
__global__ __launch_bounds__(256, 2) void k_gemmfill(const float* __restrict__ X,
                                                     const int* __restrict__ ei) {
    __shared__ uint4  As4[512];     // A fragments (8KB)
    __shared__ float4 Wfs[1024];    // W fragments, 2 buffers (16KB)

    int bid = blockIdx.x;
    if (bid % 5 != 0) {                     // ---- fill branch (interleaved) ----
        int fid = bid - bid / 5 - 1;
        int e = fid * 256 + threadIdx.x;
        if (e < NE) {
            int r = ei[e];
            int c = ei[NE + e];
            int pos = g_ptr[c] + atomicAdd(&g_fill[c], 1);
            g_srcs[pos] = r;
        }
        return;
    }

    // ---- gemm branch ----
    int gid  = bid / 5;
    int tid  = threadIdx.x;
    int warp = tid >> 5, lane = tid & 31;
    int g    = lane >> 2, tig = lane & 3;
    int bm   = gid * 128;

    unsigned wAddr = (unsigned)__cvta_generic_to_shared(&Wfs[0]);
    unsigned* As = reinterpret_cast<unsigned*>(As4);

    int cRow = tid >> 3;                 // staging: 4 rows (stride 32), 1 float4 each
    int cb   = (tid & 7) * 4;            // col base within 32-wide tile

    auto ldgA = [&](int t, float4* pre) {
#pragma unroll
        for (int i = 0; i < 4; ++i) {
            int row = cRow + (i << 5);
            pre[i] = (bm + row < NN)
                ? *(const float4*)(X + (size_t)(bm + row) * 128 + t * 32 + cb)
                : make_float4(0.f, 0.f, 0.f, 0.f);
        }
    };
    auto stsA = [&](const float4* pre) {
#pragma unroll
        for (int i = 0; i < 4; ++i) {
            int row = cRow + (i << 5);
            int rr = row & 15, gg = rr & 7, hi = rr >> 3, rg = row >> 4;
            float4 v = pre[i];
            {
                int c0 = cb;
                int s = (c0 >> 4) & 1, j = (c0 >> 3) & 1, tg = (c0 >> 1) & 3;
                As[((rg * 2 + s) * 32 + gg * 4 + tg) * 4 + j * 2 + hi] = bf2u(v.x, v.y);
            }
            {
                int c1 = cb + 2;
                int s = (c1 >> 4) & 1, j = (c1 >> 3) & 1, tg = (c1 >> 1) & 3;
                As[((rg * 2 + s) * 32 + gg * 4 + tg) * 4 + j * 2 + hi] = bf2u(v.z, v.w);
            }
        }
    };
    auto copyW = [&](int t, int buf) {   // 512 float4 per 32-K tile
        const float4* wsrc = g_wfragh + t * 512;
#pragma unroll
        for (int i = 0; i < 2; ++i) {
            int idx = tid + i * 256;
            cpa16(wAddr + (buf * 512 + idx) * 16, wsrc + idx, 16);
        }
        cpa_commit();
    };

    float c[16][4];
#pragma unroll
    for (int nt = 0; nt < 16; ++nt)
#pragma unroll
        for (int j = 0; j < 4; ++j) c[nt][j] = 0.f;

    float4 pre[4];
    copyW(0, 0);
    ldgA(0, pre);

#pragma unroll
    for (int t = 0; t < 4; ++t) {
        stsA(pre);                       // tile t into As (prev compute synced)
        if (t < 3) {
            ldgA(t + 1, pre);
            copyW(t + 1, (t + 1) & 1);
            cpa_wait<1>();               // W(t) arrived
        } else {
            cpa_wait<0>();
        }
        __syncthreads();

        uint4 fa0 = As4[(warp * 2 + 0) * 32 + lane];   // k-step 0 fragment
        uint4 fa1 = As4[(warp * 2 + 1) * 32 + lane];   // k-step 1 fragment
#pragma unroll
        for (int s = 0; s < 2; ++s) {
            uint4 fa = s ? fa1 : fa0;
            const float4* wp = &Wfs[(t & 1) * 512 + s * 256 + lane];
#pragma unroll
            for (int ntp = 0; ntp < 8; ++ntp) {
                float4 bf = wp[ntp * 32];
                mma_bf16(c[2 * ntp][0], c[2 * ntp][1], c[2 * ntp][2], c[2 * ntp][3],
                         fa.x, fa.y, fa.z, fa.w,
                         __float_as_uint(bf.x), __float_as_uint(bf.y));
                mma_bf16(c[2 * ntp + 1][0], c[2 * ntp + 1][1], c[2 * ntp + 1][2], c[2 * ntp + 1][3],
                         fa.x, fa.y, fa.z, fa.w,
                         __float_as_uint(bf.z), __float_as_uint(bf.w));
            }
        }
        __syncthreads();                 // done reading As before next stsA
    }

    // epilogue: scale by dinv[row], store bf16
    int r0 = bm + warp * 16 + g;
    int r1 = r0 + 8;
    float d0 = (r0 < NN) ? g_dinv[r0] : 0.f;
    float d1 = (r1 < NN) ? g_dinv[r1] : 0.f;
#pragma unroll
    for (int nt = 0; nt < 16; ++nt) {
        int col = nt * 8 + tig * 2;
        if (r0 < NN) {
            __nv_bfloat162 v = __floats2bfloat162_rn(d0 * c[nt][0], d0 * c[nt][1]);
            *(__nv_bfloat162*)(g_h1b + (size_t)r0 * 128 + col) = v;
        }
        if (r1 < NN) {
            __nv_bfloat162 v = __floats2bfloat162_rn(d1 * c[nt][2], d1 * c[nt][3]);
            *(__nv_bfloat162*)(g_h1b + (size_t)r1 * 128 + col) = v;
        }
    }
}

// ---------- launch 5: agg1 + skinny GEMM2; f32x2 accumulation -------------
__global__ void k_agg1h2(const float* __restrict__ b1,
                         const float* __restrict__ W2) {
    int warp = (blockIdx.x * blockDim.x + threadIdx.x) >> 5;
    int lane = threadIdx.x & 31;
    if (warp >= NN) return;
    int p0 = g_ptr[warp], p1 = g_ptr[warp + 1];
    float dc = g_dinv[warp];

    ull acc01, acc23;
    {
        uint2 raw = *(const uint2*)(g_h1b + (size_t)warp * 128 + lane * 4);
        acc01 = bfpair(raw.x);
        acc23 = bfpair(raw.y);
    }
    int e = p0;
    for (; e + 4 <= p1; e += 4) {
        int r0 = g_srcs[e], r1 = g_srcs[e + 1], r2 = g_srcs[e + 2], r3 = g_srcs[e + 3];
        uint2 q0 = *(const uint2*)(g_h1b + (size_t)r0 * 128 + lane * 4);
        uint2 q1 = *(const uint2*)(g_h1b + (size_t)r1 * 128 + lane * 4);
        uint2 q2 = *(const uint2*)(g_h1b + (size_t)r2 * 128 + lane * 4);
        uint2 q3 = *(const uint2*)(g_h1b + (size_t)r3 * 128 + lane * 4);
        addf2(acc01, bfpair(q0.x)); addf2(acc23, bfpair(q0.y));
        addf2(acc01, bfpair(q1.x)); addf2(acc23, bfpair(q1.y));
        addf2(acc01, bfpair(q2.x)); addf2(acc23, bfpair(q2.y));
        addf2(acc01, bfpair(q3.x)); addf2(acc23, bfpair(q3.y));
    }
    for (; e < p1; ++e) {
        int r = g_srcs[e];
        uint2 q = *(const uint2*)(g_h1b + (size_t)r * 128 + lane * 4);
        addf2(acc01, bfpair(q.x));
        addf2(acc23, bfpair(q.y));
    }

    float2 f01 = unpk(acc01);
    float2 f23 = unpk(acc23);
    float4 bb = ((const float4*)b1)[lane];
    float ax = fmaxf(fmaf(dc, f01.x, bb.x), 0.f);
    float ay = fmaxf(fmaf(dc, f01.y, bb.y), 0.f);
    float az = fmaxf(fmaf(dc, f23.x, bb.z), 0.f);
    float aw = fmaxf(fmaf(dc, f23.y, bb.w), 0.f);

    const float4* w2p = (const float4*)(W2 + lane * 8);
    float4 wA = w2p[0];
    float4 wB = w2p[1];
    float s0 = ax * wA.x + ay * wA.z + az * wB.x + aw * wB.z;
    float s1 = ax * wA.y + ay * wA.w + az * wB.y + aw * wB.w;
#pragma unroll
    for (int off = 16; off > 0; off >>= 1) {
        s0 += __shfl_xor_sync(0xffffffffu, s0, off);
        s1 += __shfl_xor_sync(0xffffffffu, s1, off);
    }
    if (lane == 0) {
        g_h2[warp * 2 + 0] = dc * s0;
        g_h2[warp * 2 + 1] = dc * s1;
    }
}

// ---------- launch 6: layer-2 aggregation + mean-pool partials ------------
__global__ void k_agg2pool(const float* __restrict__ b2,
                           const int* __restrict__ batch) {
    __shared__ float s_sums[NG * NC];
    __shared__ float s_cnt[NG];
    int t = threadIdx.x;
    if (t < NG * NC) s_sums[t] = 0.f;
    if (t < NG) s_cnt[t] = 0.f;
    __syncthreads();

    int i = blockIdx.x * blockDim.x + t;
    if (i < NN) {
        float d = g_dinv[i];
        float a0 = g_h2[i * 2 + 0];
        float a1 = g_h2[i * 2 + 1];
        int p0 = g_ptr[i], p1 = g_ptr[i + 1];
        int e = p0;
        for (; e + 4 <= p1; e += 4) {
            int r0 = g_srcs[e], r1 = g_srcs[e + 1], r2 = g_srcs[e + 2], r3 = g_srcs[e + 3];
            float2 h0 = *(const float2*)(g_h2 + r0 * 2);
            float2 h1 = *(const float2*)(g_h2 + r1 * 2);
            float2 h2 = *(const float2*)(g_h2 + r2 * 2);
            float2 h3 = *(const float2*)(g_h2 + r3 * 2);
            a0 += (h0.x + h1.x) + (h2.x + h3.x);
            a1 += (h0.y + h1.y) + (h2.y + h3.y);
        }
        for (; e < p1; ++e) {
            float2 h = *(const float2*)(g_h2 + g_srcs[e] * 2);
            a0 += h.x; a1 += h.y;
        }
        a0 = fmaf(d, a0, b2[0]);
        a1 = fmaf(d, a1, b2[1]);
        int g = batch[i];
        atomicAdd(&s_sums[g * 2 + 0], a0);
        atomicAdd(&s_sums[g * 2 + 1], a1);
        atomicAdd(&s_cnt[g], 1.f);
    }
    __syncthreads();
    if (t < NG * NC) atomicAdd(&g_sums[t], s_sums[t]);
    if (t < NG) atomicAdd(&g_cnts[t], s_cnt[t]);
}

// ---------- launch 7: log_softmax + state re-zero --------------------------
__global__ void k_finalclean(float* __restrict__ out) {
    int i = blockIdx.x * blockDim.x + threadIdx.x;
    if (i < NN) { g_deg[i] = 0; g_fill[i] = 0; }
    if (blockIdx.x == 0) {
        int t = threadIdx.x;
        if (t < NG) {
            float c = fmaxf(g_cnts[t], 1.f);
            float p0 = g_sums[t * 2 + 0] / c;
            float p1 = g_sums[t * 2 + 1] / c;
            float m = fmaxf(p0, p1);
            float l = m + logf(expf(p0 - m) + expf(p1 - m));
            out[t * 2 + 0] = p0 - l;
            out[t * 2 + 1] = p1 - l;
            g_sums[t * 2 + 0] = 0.f;
            g_sums[t * 2 + 1] = 0.f;
            g_cnts[t] = 0.f;
        }
    }
}

// ---------------- launch --------------------------------------------------
extern "C" void kernel_launch(void* const* d_in, const int* in_sizes, int n_in,
                              void* d_out, int out_size) {
    const float* x     = (const float*)d_in[0];
    const int*   ei    = (const int*)d_in[1];     // int32 (JAX x64 disabled)
    const int*   batch = (const int*)d_in[2];
    const float* W1    = (const float*)d_in[3];
    const float* b1    = (const float*)d_in[4];
    const float* W2    = (const float*)d_in[5];
    const float* b2    = (const float*)d_in[6];
    float* out = (float*)d_out;

    k_histinit<<<HB + 8, 256>>>(ei, W1);
    k_scanA<<<25, 1024>>>();
    k_spineAdd<<<(NN + 1023) / 1024, 1024>>>();
    k_gemmfill<<<GB + FB, 256>>>(x, ei);          // 4th -> ncu slot
    k_agg1h2<<<(NN * 32 + 255) / 256, 256>>>(b1, W2);
    k_agg2pool<<<(NN + 255) / 256, 256>>>(b2, batch);
    k_finalclean<<<(NN + 255) / 256, 256>>>(out);
}

// round 16
// speedup vs baseline: 1.0958x; 1.0958x over previous
#include <cuda_runtime.h>
#include <cuda_bf16.h>
#include <math.h>

#define NN 100000
#define NE 800000
#define NG 16
#define NF 128
#define NH 128
#define NC 2

#define GB 782            // gemm blocks in k_gemmfill
#define FB 3125           // fill blocks
#define HB 3125           // hist blocks

typedef unsigned long long ull;

// ---------------- persistent scratch (alloc-free rule: __device__ globals) ---
__device__ int            g_deg[NN];
__device__ float          g_dinv[NN];
__device__ int            g_ptr[NN + 1];
__device__ int            g_fill[NN];
__device__ int            g_srcs[NE];
__device__ __nv_bfloat16  g_h1b[(size_t)NN * NF];  // bf16(dinv * (x @ W1))
__device__ float          g_h2[NN * NC];           // dinv * (act @ W2)
__device__ float          g_sums[NG * NC];
__device__ float          g_cnts[NG];
__device__ int            g_bsum[32];
__device__ float4         g_wfragh[2048];          // W1 bf16 m16n8k16 fragments

// ---------------- helpers -------------------------------------------------
__device__ __forceinline__ void mma_bf16(float& c0, float& c1, float& c2, float& c3,
                                         unsigned a0, unsigned a1, unsigned a2, unsigned a3,
                                         unsigned b0, unsigned b1) {
    asm("mma.sync.aligned.m16n8k16.row.col.f32.bf16.bf16.f32 "
        "{%0,%1,%2,%3}, {%4,%5,%6,%7}, {%8,%9}, {%0,%1,%2,%3};"
        : "+f"(c0), "+f"(c1), "+f"(c2), "+f"(c3)
        : "r"(a0), "r"(a1), "r"(a2), "r"(a3), "r"(b0), "r"(b1));
}

__device__ __forceinline__ unsigned bf2u(float a, float b) {
    __nv_bfloat162 h = __floats2bfloat162_rn(a, b);
    return *reinterpret_cast<unsigned*>(&h);
}

__device__ __forceinline__ __nv_bfloat162 u2b(unsigned u) {
    return *reinterpret_cast<__nv_bfloat162*>(&u);
}

__device__ __forceinline__ void cpa16(unsigned dst, const void* src, int srcsz) {
    asm volatile("cp.async.cg.shared.global [%0], [%1], 16, %2;"
                 :: "r"(dst), "l"(src), "r"(srcsz));
}
__device__ __forceinline__ void cpa_commit() {
    asm volatile("cp.async.commit_group;");
}
template <int N>
__device__ __forceinline__ void cpa_wait() {
    asm volatile("cp.async.wait_group %0;" :: "n"(N));
}

// ---------- launch 1: degree histogram  ||  W1 bf16 fragment transform ----
__global__ void k_histinit(const int* __restrict__ ei, const float* __restrict__ W) {
    int b = blockIdx.x;
    if (b < HB) {
        int e = b * 256 + threadIdx.x;
        if (e < NE) atomicAdd(&g_deg[ei[NE + e]], 1);
    } else {
        int i = (b - HB) * 256 + threadIdx.x;       // 0..2047
        int lane = i & 31, ntp = (i >> 5) & 7, sg = i >> 8;
        int g = lane >> 2, tig = lane & 3;
        int k0 = sg * 16;
        int n0 = ntp * 16 + g, n1 = n0 + 8;
        float4 f;
        f.x = __uint_as_float(bf2u(W[(k0 + 2*tig    ) * 128 + n0], W[(k0 + 2*tig + 1) * 128 + n0]));
        f.y = __uint_as_float(bf2u(W[(k0 + 2*tig + 8) * 128 + n0], W[(k0 + 2*tig + 9) * 128 + n0]));
        f.z = __uint_as_float(bf2u(W[(k0 + 2*tig    ) * 128 + n1], W[(k0 + 2*tig + 1) * 128 + n1]));
        f.w = __uint_as_float(bf2u(W[(k0 + 2*tig + 8) * 128 + n1], W[(k0 + 2*tig + 9) * 128 + n1]));
        g_wfragh[i] = f;
    }
}

// ---------- launch 2: block-parallel scan of deg -> ptr (+dinv) -----------
__global__ void k_scanA() {
    __shared__ int wsum[32];
    int b = blockIdx.x, t = threadIdx.x;
    int lane = t & 31, wid = t >> 5;
    int base = b * 4096 + t * 4;
    int v[4]; int s = 0;
#pragma unroll
    for (int j = 0; j < 4; ++j) {
        v[j] = (base + j < NN) ? g_deg[base + j] : 0;
        s += v[j];
    }
#pragma unroll
    for (int j = 0; j < 4; ++j)
        if (base + j < NN) g_dinv[base + j] = rsqrtf((float)(v[j] + 1));
    int inc = s;
#pragma unroll
    for (int off = 1; off < 32; off <<= 1) {
        int n = __shfl_up_sync(0xffffffffu, inc, off);
        if (lane >= off) inc += n;
    }
    if (lane == 31) wsum[wid] = inc;
    __syncthreads();
    if (wid == 0) {
        int w = wsum[lane];
        int wi = w;
#pragma unroll
        for (int off = 1; off < 32; off <<= 1) {
            int n = __shfl_up_sync(0xffffffffu, wi, off);
            if (lane >= off) wi += n;
        }
        wsum[lane] = wi - w;
    }
    __syncthreads();
    int excl = inc - s + wsum[wid];
    if (t == 1023) g_bsum[b] = inc + wsum[31];
    int run = excl;
#pragma unroll
    for (int j = 0; j < 4; ++j) {
        if (base + j < NN) g_ptr[base + j] = run;
        run += v[j];
    }
}

// ---------- launch 3: spine scan folded into the add pass -----------------
__global__ void k_spineAdd() {
    __shared__ int off[32];
    int t = threadIdx.x;
    if (t < 32) {
        int v = (t < 25) ? g_bsum[t] : 0;
        int inc = v;
#pragma unroll
        for (int o = 1; o < 32; o <<= 1) {
            int n = __shfl_up_sync(0xffffffffu, inc, o);
            if (t >= o) inc += n;
        }
        off[t] = inc - v;
    }
    __syncthreads();
    int i = blockIdx.x * 1024 + t;
    if (i < NN) g_ptr[i] += off[i >> 12];
    if (i == 0) g_ptr[NN] = NE;
}

// ---------- launch 4 (ncu slot): bf16 MMA GEMM1 || CSR-fill (appended) ----
__global__ __launch_bounds__(256, 2) void k_gemmfill(const float* __restrict__ X,
                                                     const int* __restrict__ ei) {
    __shared__ uint4  As4[512];     // A fragments (8KB)
    __shared__ float4 Wfs[1024];    // W fragments, 2 buffers (16KB)

    if (blockIdx.x >= GB) {                 // ---- fill branch ----
        int e = (blockIdx.x - GB) * 256 + threadIdx.x;
        if (e < NE) {
            int r = ei[e];
            int c = ei[NE + e];
            int pos = g_ptr[c] + atomicAdd(&g_fill[c], 1);
            g_srcs[pos] = r;
        }
        return;
    }

    // ---- gemm branch ----
    int tid  = threadIdx.x;
    int warp = tid >> 5, lane = tid & 31;
    int g    = lane >> 2, tig = lane & 3;
    int bm   = blockIdx.x * 128;

    unsigned wAddr = (unsigned)__cvta_generic_to_shared(&Wfs[0]);
    unsigned* As = reinterpret_cast<unsigned*>(As4);

    int cRow = tid >> 3;                 // staging: 4 rows (stride 32), 1 float4 each
    int cb   = (tid & 7) * 4;            // col base within 32-wide tile

    auto ldgA = [&](int t, float4* pre) {
#pragma unroll
        for (int i = 0; i < 4; ++i) {
            int row = cRow + (i << 5);
            pre[i] = (bm + row < NN)
                ? *(const float4*)(X + (size_t)(bm + row) * 128 + t * 32 + cb)
                : make_float4(0.f, 0.f, 0.f, 0.f);
        }
    };
    auto stsA = [&](const float4* pre) {
#pragma unroll
        for (int i = 0; i < 4; ++i) {
            int row = cRow + (i << 5);
            int rr = row & 15, gg = rr & 7, hi = rr >> 3, rg = row >> 4;
            float4 v = pre[i];
            {
                int c0 = cb;
                int s = (c0 >> 4) & 1, j = (c0 >> 3) & 1, tg = (c0 >> 1) & 3;
                As[((rg * 2 + s) * 32 + gg * 4 + tg) * 4 + j * 2 + hi] = bf2u(v.x, v.y);
            }
            {
                int c1 = cb + 2;
                int s = (c1 >> 4) & 1, j = (c1 >> 3) & 1, tg = (c1 >> 1) & 3;
                As[((rg * 2 + s) * 32 + gg * 4 + tg) * 4 + j * 2 + hi] = bf2u(v.z, v.w);
            }
        }
    };
    auto copyW = [&](int t, int buf) {   // 512 float4 per 32-K tile
        const float4* wsrc = g_wfragh + t * 512;
#pragma unroll
        for (int i = 0; i < 2; ++i) {
            int idx = tid + i * 256;
            cpa16(wAddr + (buf * 512 + idx) * 16, wsrc + idx, 16);
        }
        cpa_commit();
    };

    float c[16][4];
#pragma unroll
    for (int nt = 0; nt < 16; ++nt)
#pragma unroll
        for (int j = 0; j < 4; ++j) c[nt][j] = 0.f;

    float4 pre[4];
    copyW(0, 0);
    ldgA(0, pre);

#pragma unroll
    for (int t = 0; t < 4; ++t) {
        stsA(pre);
        if (t < 3) {
            ldgA(t + 1, pre);
            copyW(t + 1, (t + 1) & 1);
            cpa_wait<1>();
        } else {
            cpa_wait<0>();
        }
        __syncthreads();

        uint4 fa0 = As4[(warp * 2 + 0) * 32 + lane];
        uint4 fa1 = As4[(warp * 2 + 1) * 32 + lane];
#pragma unroll
        for (int s = 0; s < 2; ++s) {
            uint4 fa = s ? fa1 : fa0;
            const float4* wp = &Wfs[(t & 1) * 512 + s * 256 + lane];
#pragma unroll
            for (int ntp = 0; ntp < 8; ++ntp) {
                float4 bf = wp[ntp * 32];
                mma_bf16(c[2 * ntp][0], c[2 * ntp][1], c[2 * ntp][2], c[2 * ntp][3],
                         fa.x, fa.y, fa.z, fa.w,
                         __float_as_uint(bf.x), __float_as_uint(bf.y));
                mma_bf16(c[2 * ntp + 1][0], c[2 * ntp + 1][1], c[2 * ntp + 1][2], c[2 * ntp + 1][3],
                         fa.x, fa.y, fa.z, fa.w,
                         __float_as_uint(bf.z), __float_as_uint(bf.w));
            }
        }
        __syncthreads();
    }

    // epilogue: scale by dinv[row], store bf16
    int r0 = bm + warp * 16 + g;
    int r1 = r0 + 8;
    float d0 = (r0 < NN) ? g_dinv[r0] : 0.f;
    float d1 = (r1 < NN) ? g_dinv[r1] : 0.f;
#pragma unroll
    for (int nt = 0; nt < 16; ++nt) {
        int col = nt * 8 + tig * 2;
        if (r0 < NN) {
            __nv_bfloat162 v = __floats2bfloat162_rn(d0 * c[nt][0], d0 * c[nt][1]);
            *(__nv_bfloat162*)(g_h1b + (size_t)r0 * 128 + col) = v;
        }
        if (r1 < NN) {
            __nv_bfloat162 v = __floats2bfloat162_rn(d1 * c[nt][2], d1 * c[nt][3]);
            *(__nv_bfloat162*)(g_h1b + (size_t)r1 * 128 + col) = v;
        }
    }
}

// ---------- launch 5: agg1 + skinny GEMM2; packed bf16 accumulation -------
__global__ void k_agg1h2(const float* __restrict__ b1,
                         const float* __restrict__ W2) {
    int warp = (blockIdx.x * blockDim.x + threadIdx.x) >> 5;
    int lane = threadIdx.x & 31;
    if (warp >= NN) return;
    int p0 = g_ptr[warp], p1 = g_ptr[warp + 1];
    float dc = g_dinv[warp];

    __nv_bfloat162 a01, a23;     // packed bf16 accumulators (1 HADD2/word/edge)
    {
        uint2 raw = *(const uint2*)(g_h1b + (size_t)warp * 128 + lane * 4);
        a01 = u2b(raw.x);
        a23 = u2b(raw.y);
    }
    int e = p0;
    for (; e + 4 <= p1; e += 4) {       // 4 independent gathers in flight
        int r0 = g_srcs[e], r1 = g_srcs[e + 1], r2 = g_srcs[e + 2], r3 = g_srcs[e + 3];
        uint2 q0 = *(const uint2*)(g_h1b + (size_t)r0 * 128 + lane * 4);
        uint2 q1 = *(const uint2*)(g_h1b + (size_t)r1 * 128 + lane * 4);
        uint2 q2 = *(const uint2*)(g_h1b + (size_t)r2 * 128 + lane * 4);
        uint2 q3 = *(const uint2*)(g_h1b + (size_t)r3 * 128 + lane * 4);
        a01 = __hadd2(a01, u2b(q0.x)); a23 = __hadd2(a23, u2b(q0.y));
        a01 = __hadd2(a01, u2b(q1.x)); a23 = __hadd2(a23, u2b(q1.y));
        a01 = __hadd2(a01, u2b(q2.x)); a23 = __hadd2(a23, u2b(q2.y));
        a01 = __hadd2(a01, u2b(q3.x)); a23 = __hadd2(a23, u2b(q3.y));
    }
    for (; e < p1; ++e) {
        int r = g_srcs[e];
        uint2 q = *(const uint2*)(g_h1b + (size_t)r * 128 + lane * 4);
        a01 = __hadd2(a01, u2b(q.x));
        a23 = __hadd2(a23, u2b(q.y));
    }

    float2 f01 = __bfloat1622float2(a01);
    float2 f23 = __bfloat1622float2(a23);
    float4 bb = ((const float4*)b1)[lane];
    float ax = fmaxf(fmaf(dc, f01.x, bb.x), 0.f);
    float ay = fmaxf(fmaf(dc, f01.y, bb.y), 0.f);
    float az = fmaxf(fmaf(dc, f23.x, bb.z), 0.f);
    float aw = fmaxf(fmaf(dc, f23.y, bb.w), 0.f);

    const float4* w2p = (const float4*)(W2 + lane * 8);
    float4 wA = w2p[0];
    float4 wB = w2p[1];
    float s0 = ax * wA.x + ay * wA.z + az * wB.x + aw * wB.z;
    float s1 = ax * wA.y + ay * wA.w + az * wB.y + aw * wB.w;
#pragma unroll
    for (int off = 16; off > 0; off >>= 1) {
        s0 += __shfl_xor_sync(0xffffffffu, s0, off);
        s1 += __shfl_xor_sync(0xffffffffu, s1, off);
    }
    if (lane == 0) {
        g_h2[warp * 2 + 0] = dc * s0;
        g_h2[warp * 2 + 1] = dc * s1;
    }
}

// ---------- launch 6: layer-2 aggregation + mean-pool partials ------------
__global__ void k_agg2pool(const float* __restrict__ b2,
                           const int* __restrict__ batch) {
    __shared__ float s_sums[NG * NC];
    __shared__ float s_cnt[NG];
    int t = threadIdx.x;
    if (t < NG * NC) s_sums[t] = 0.f;
    if (t < NG) s_cnt[t] = 0.f;
    __syncthreads();

    int i = blockIdx.x * blockDim.x + t;
    if (i < NN) {
        float d = g_dinv[i];
        float a0 = g_h2[i * 2 + 0];
        float a1 = g_h2[i * 2 + 1];
        int p0 = g_ptr[i], p1 = g_ptr[i + 1];
        int e = p0;
        for (; e + 4 <= p1; e += 4) {
            int r0 = g_srcs[e], r1 = g_srcs[e + 1], r2 = g_srcs[e + 2], r3 = g_srcs[e + 3];
            float2 h0 = *(const float2*)(g_h2 + r0 * 2);
            float2 h1 = *(const float2*)(g_h2 + r1 * 2);
            float2 h2 = *(const float2*)(g_h2 + r2 * 2);
            float2 h3 = *(const float2*)(g_h2 + r3 * 2);
            a0 += (h0.x + h1.x) + (h2.x + h3.x);
            a1 += (h0.y + h1.y) + (h2.y + h3.y);
        }
        for (; e < p1; ++e) {
            float2 h = *(const float2*)(g_h2 + g_srcs[e] * 2);
            a0 += h.x; a1 += h.y;
        }
        a0 = fmaf(d, a0, b2[0]);
        a1 = fmaf(d, a1, b2[1]);
        int g = batch[i];
        atomicAdd(&s_sums[g * 2 + 0], a0);
        atomicAdd(&s_sums[g * 2 + 1], a1);
        atomicAdd(&s_cnt[g], 1.f);
    }
    __syncthreads();
    if (t < NG * NC) atomicAdd(&g_sums[t], s_sums[t]);
    if (t < NG) atomicAdd(&g_cnts[t], s_cnt[t]);
}

// ---------- launch 7: log_softmax + state re-zero --------------------------
__global__ void k_finalclean(float* __restrict__ out) {
    int i = blockIdx.x * blockDim.x + threadIdx.x;
    if (i < NN) { g_deg[i] = 0; g_fill[i] = 0; }
    if (blockIdx.x == 0) {
        int t = threadIdx.x;
        if (t < NG) {
            float c = fmaxf(g_cnts[t], 1.f);
            float p0 = g_sums[t * 2 + 0] / c;
            float p1 = g_sums[t * 2 + 1] / c;
            float m = fmaxf(p0, p1);
            float l = m + logf(expf(p0 - m) + expf(p1 - m));
            out[t * 2 + 0] = p0 - l;
            out[t * 2 + 1] = p1 - l;
            g_sums[t * 2 + 0] = 0.f;
            g_sums[t * 2 + 1] = 0.f;
            g_cnts[t] = 0.f;
        }
    }
}

// ---------------- launch --------------------------------------------------
extern "C" void kernel_launch(void* const* d_in, const int* in_sizes, int n_in,
                              void* d_out, int out_size) {
    const float* x     = (const float*)d_in[0];
    const int*   ei    = (const int*)d_in[1];     // int32 (JAX x64 disabled)
    const int*   batch = (const int*)d_in[2];
    const float* W1    = (const float*)d_in[3];
    const float* b1    = (const float*)d_in[4];
    const float* W2    = (const float*)d_in[5];
    const float* b2    = (const float*)d_in[6];
    float* out = (float*)d_out;

    k_histinit<<<HB + 8, 256>>>(ei, W1);
    k_scanA<<<25, 1024>>>();
    k_spineAdd<<<(NN + 1023) / 1024, 1024>>>();
    k_gemmfill<<<GB + FB, 256>>>(x, ei);          // 4th -> ncu slot
    k_agg1h2<<<(NN * 32 + 255) / 256, 256>>>(b1, W2);
    k_agg2pool<<<(NN + 255) / 256, 256>>>(b2, batch);
    k_finalclean<<<(NN + 255) / 256, 256>>>(out);
}

// round 17
// speedup vs baseline: 1.1125x; 1.0152x over previous
#include <cuda_runtime.h>
#include <cuda_bf16.h>
#include <math.h>

#define NN 100000
#define NE 800000
#define NG 16
#define NF 128
#define NH 128
#define NC 2

#define GB 782            // gemm blocks in k_gemmfill
#define FB 3125           // fill blocks
#define HB 3125           // hist blocks

#define GSMEM (96 * 1024) // 64KB A (f32, swizzled) + 32KB W (bf16 frags)

typedef unsigned long long ull;

// ---------------- persistent scratch (alloc-free rule: __device__ globals) ---
__device__ int            g_deg[NN];
__device__ float          g_dinv[NN];
__device__ int            g_ptr[NN + 1];
__device__ int            g_fill[NN];
__device__ int            g_srcs[NE];
__device__ __nv_bfloat16  g_h1b[(size_t)NN * NF];  // bf16(dinv * (x @ W1))
__device__ float          g_h2[NN * NC];           // dinv * (act @ W2)
__device__ float          g_sums[NG * NC];
__device__ float          g_cnts[NG];
__device__ int            g_bsum[32];
__device__ float4         g_wfragh[2048];          // W1 bf16 m16n8k16 fragments

// ---------------- helpers -------------------------------------------------
__device__ __forceinline__ void mma_bf16(float& c0, float& c1, float& c2, float& c3,
                                         unsigned a0, unsigned a1, unsigned a2, unsigned a3,
                                         unsigned b0, unsigned b1) {
    asm("mma.sync.aligned.m16n8k16.row.col.f32.bf16.bf16.f32 "
        "{%0,%1,%2,%3}, {%4,%5,%6,%7}, {%8,%9}, {%0,%1,%2,%3};"
        : "+f"(c0), "+f"(c1), "+f"(c2), "+f"(c3)
        : "r"(a0), "r"(a1), "r"(a2), "r"(a3), "r"(b0), "r"(b1));
}

__device__ __forceinline__ unsigned bf2u(float a, float b) {
    __nv_bfloat162 h = __floats2bfloat162_rn(a, b);
    return *reinterpret_cast<unsigned*>(&h);
}

__device__ __forceinline__ __nv_bfloat162 u2b(unsigned u) {
    return *reinterpret_cast<__nv_bfloat162*>(&u);
}

__device__ __forceinline__ void cpa16(unsigned dst, const void* src, int srcsz) {
    asm volatile("cp.async.cg.shared.global [%0], [%1], 16, %2;"
                 :: "r"(dst), "l"(src), "r"(srcsz));
}
__device__ __forceinline__ void cpa_commit() {
    asm volatile("cp.async.commit_group;");
}
template <int N>
__device__ __forceinline__ void cpa_wait() {
    asm volatile("cp.async.wait_group %0;" :: "n"(N));
}

// ---------- launch 1: degree histogram  ||  W1 bf16 fragment transform ----
__global__ void k_histinit(const int* __restrict__ ei, const float* __restrict__ W) {
    int b = blockIdx.x;
    if (b < HB) {
        int e = b * 256 + threadIdx.x;
        if (e < NE) atomicAdd(&g_deg[ei[NE + e]], 1);
    } else {
        int i = (b - HB) * 256 + threadIdx.x;       // 0..2047
        int lane = i & 31, ntp = (i >> 5) & 7, sg = i >> 8;
        int g = lane >> 2, tig = lane & 3;
        int k0 = sg * 16;
        int n0 = ntp * 16 + g, n1 = n0 + 8;
        float4 f;
        f.x = __uint_as_float(bf2u(W[(k0 + 2*tig    ) * 128 + n0], W[(k0 + 2*tig + 1) * 128 + n0]));
        f.y = __uint_as_float(bf2u(W[(k0 + 2*tig + 8) * 128 + n0], W[(k0 + 2*tig + 9) * 128 + n0]));
        f.z = __uint_as_float(bf2u(W[(k0 + 2*tig    ) * 128 + n1], W[(k0 + 2*tig + 1) * 128 + n1]));
        f.w = __uint_as_float(bf2u(W[(k0 + 2*tig + 8) * 128 + n1], W[(k0 + 2*tig + 9) * 128 + n1]));
        g_wfragh[i] = f;
    }
}

// ---------- launch 2: block-parallel scan of deg -> ptr (+dinv) -----------
__global__ void k_scanA() {
    __shared__ int wsum[32];
    int b = blockIdx.x, t = threadIdx.x;
    int lane = t & 31, wid = t >> 5;
    int base = b * 4096 + t * 4;
    int v[4]; int s = 0;
#pragma unroll
    for (int j = 0; j < 4; ++j) {
        v[j] = (base + j < NN) ? g_deg[base + j] : 0;
        s += v[j];
    }
#pragma unroll
    for (int j = 0; j < 4; ++j)
        if (base + j < NN) g_dinv[base + j] = rsqrtf((float)(v[j] + 1));
    int inc = s;
#pragma unroll
    for (int off = 1; off < 32; off <<= 1) {
        int n = __shfl_up_sync(0xffffffffu, inc, off);
        if (lane >= off) inc += n;
    }
    if (lane == 31) wsum[wid] = inc;
    __syncthreads();
    if (wid == 0) {
        int w = wsum[lane];
        int wi = w;
#pragma unroll
        for (int off = 1; off < 32; off <<= 1) {
            int n = __shfl_up_sync(0xffffffffu, wi, off);
            if (lane >= off) wi += n;
        }
        wsum[lane] = wi - w;
    }
    __syncthreads();
    int excl = inc - s + wsum[wid];
    if (t == 1023) g_bsum[b] = inc + wsum[31];
    int run = excl;
#pragma unroll
    for (int j = 0; j < 4; ++j) {
        if (base + j < NN) g_ptr[base + j] = run;
        run += v[j];
    }
}

// ---------- launch 3: spine scan folded into the add pass -----------------
__global__ void k_spineAdd() {
    __shared__ int off[32];
    int t = threadIdx.x;
    if (t < 32) {
        int v = (t < 25) ? g_bsum[t] : 0;
        int inc = v;
#pragma unroll
        for (int o = 1; o < 32; o <<= 1) {
            int n = __shfl_up_sync(0xffffffffu, inc, o);
            if (t >= o) inc += n;
        }
        off[t] = inc - v;
    }
    __syncthreads();
    int i = blockIdx.x * 1024 + t;
    if (i < NN) g_ptr[i] += off[i >> 12];
    if (i == 0) g_ptr[NN] = NE;
}

// ---------- launch 4 (ncu slot): bulk-async GEMM1 || CSR-fill -------------
// One cp.async volley loads ALL of A (raw f32, 64KB, XOR-swizzled) and ALL
// of W (32KB bf16 fragments); single wait+sync; then a zero-barrier mainloop
// of 8 k16-steps (LDS.64 A pairs -> bf16 cvt -> mma).
__global__ __launch_bounds__(256, 2) void k_gemmfill(const float* __restrict__ X,
                                                     const int* __restrict__ ei) {
    extern __shared__ char dsm[];

    if (blockIdx.x >= GB) {                 // ---- fill branch ----
        int e = (blockIdx.x - GB) * 256 + threadIdx.x;
        if (e < NE) {
            int r = ei[e];
            int c = ei[NE + e];
            int pos = g_ptr[c] + atomicAdd(&g_fill[c], 1);
            g_srcs[pos] = r;
        }
        return;
    }

    // ---- gemm branch ----
    int tid  = threadIdx.x;
    int warp = tid >> 5, lane = tid & 31;
    int g    = lane >> 2, tig = lane & 3;
    int bm   = blockIdx.x * 128;
    int wrow = warp * 16;

    unsigned aAddr = (unsigned)__cvta_generic_to_shared(dsm);           // A: 64KB
    unsigned wAddr = aAddr + 65536;                                     // W: 32KB

    // ---- one volley: everything this block will ever read ----
    {
        int cRow = tid >> 3;             // 32 rows per step (x4), 8 chunks/row
        int cCh  = tid & 7;
#pragma unroll
        for (int t = 0; t < 4; ++t) {    // 4 A tiles (32 cols each)
#pragma unroll
            for (int i = 0; i < 4; ++i) {
                int row = cRow + (i << 5);
                int valid = (bm + row < NN) ? 16 : 0;
                const char* src = (const char*)(X + (size_t)(bm + row) * 128 + t * 32) + cCh * 16;
                unsigned slot = (unsigned)(cCh ^ (row & 7));
                cpa16(aAddr + t * 16384 + row * 128 + slot * 16, src, valid);
            }
        }
        const float4* wsrc = g_wfragh;
#pragma unroll
        for (int i = 0; i < 8; ++i) {    // full W fragment table
            int idx = tid + i * 256;
            cpa16(wAddr + idx * 16, wsrc + idx, 16);
        }
        cpa_commit();
    }

    float c[16][4];
#pragma unroll
    for (int nt = 0; nt < 16; ++nt)
#pragma unroll
        for (int j = 0; j < 4; ++j) c[nt][j] = 0.f;

    cpa_wait<0>();
    __syncthreads();                     // the ONLY barrier

    const float*  Af = (const float*)dsm;
    const float4* Wf = (const float4*)(dsm + 65536);
    int r0 = wrow + g, r1 = r0 + 8;      // r0&7 == r1&7 == g
    int off = (tig & 1) * 2;             // float offset of k-pair within chunk

#pragma unroll
    for (int sg = 0; sg < 8; ++sg) {     // 8 k16-steps, no syncs
        int t = sg >> 1, s = sg & 1;
        const float* tb = Af + t * 4096;
        int cA = s * 4 + (tig >> 1);     // chunk of k-pair (a0/a1)
        int cB = cA + 2;                 // +8 k-values = +2 chunks (a2/a3)
        float2 p0 = *(const float2*)(tb + r0 * 32 + ((cA ^ g) << 2) + off);
        float2 p1 = *(const float2*)(tb + r1 * 32 + ((cA ^ g) << 2) + off);
        float2 p2 = *(const float2*)(tb + r0 * 32 + ((cB ^ g) << 2) + off);
        float2 p3 = *(const float2*)(tb + r1 * 32 + ((cB ^ g) << 2) + off);
        unsigned a0 = bf2u(p0.x, p0.y);
        unsigned a1 = bf2u(p1.x, p1.y);
        unsigned a2 = bf2u(p2.x, p2.y);
        unsigned a3 = bf2u(p3.x, p3.y);
        const float4* wp = Wf + sg * 256 + lane;
#pragma unroll
        for (int ntp = 0; ntp < 8; ++ntp) {
            float4 bf = wp[ntp * 32];
            mma_bf16(c[2 * ntp][0], c[2 * ntp][1], c[2 * ntp][2], c[2 * ntp][3],
                     a0, a1, a2, a3,
                     __float_as_uint(bf.x), __float_as_uint(bf.y));
            mma_bf16(c[2 * ntp + 1][0], c[2 * ntp + 1][1], c[2 * ntp + 1][2], c[2 * ntp + 1][3],
                     a0, a1, a2, a3,
                     __float_as_uint(bf.z), __float_as_uint(bf.w));
        }
    }

    // epilogue: scale by dinv[row], store bf16
    int gr0 = bm + r0;
    int gr1 = bm + r1;
    float d0 = (gr0 < NN) ? g_dinv[gr0] : 0.f;
    float d1 = (gr1 < NN) ? g_dinv[gr1] : 0.f;
#pragma unroll
    for (int nt = 0; nt < 16; ++nt) {
        int col = nt * 8 + tig * 2;
        if (gr0 < NN) {
            __nv_bfloat162 v = __floats2bfloat162_rn(d0 * c[nt][0], d0 * c[nt][1]);
            *(__nv_bfloat162*)(g_h1b + (size_t)gr0 * 128 + col) = v;
        }
        if (gr1 < NN) {
            __nv_bfloat162 v = __floats2bfloat162_rn(d1 * c[nt][2], d1 * c[nt][3]);
            *(__nv_bfloat162*)(g_h1b + (size_t)gr1 * 128 + col) = v;
        }
    }
}

// ---------- launch 5: agg1 + skinny GEMM2; packed bf16 accumulation -------
__global__ void k_agg1h2(const float* __restrict__ b1,
                         const float* __restrict__ W2) {
    int warp = (blockIdx.x * blockDim.x + threadIdx.x) >> 5;
    int lane = threadIdx.x & 31;
    if (warp >= NN) return;
    int p0 = g_ptr[warp], p1 = g_ptr[warp + 1];
    float dc = g_dinv[warp];

    __nv_bfloat162 a01, a23;     // packed bf16 accumulators
    {
        uint2 raw = *(const uint2*)(g_h1b + (size_t)warp * 128 + lane * 4);
        a01 = u2b(raw.x);
        a23 = u2b(raw.y);
    }
    int e = p0;
    for (; e + 4 <= p1; e += 4) {       // 4 independent gathers in flight
        int r0 = g_srcs[e], r1 = g_srcs[e + 1], r2 = g_srcs[e + 2], r3 = g_srcs[e + 3];
        uint2 q0 = *(const uint2*)(g_h1b + (size_t)r0 * 128 + lane * 4);
        uint2 q1 = *(const uint2*)(g_h1b + (size_t)r1 * 128 + lane * 4);
        uint2 q2 = *(const uint2*)(g_h1b + (size_t)r2 * 128 + lane * 4);
        uint2 q3 = *(const uint2*)(g_h1b + (size_t)r3 * 128 + lane * 4);
        a01 = __hadd2(a01, u2b(q0.x)); a23 = __hadd2(a23, u2b(q0.y));
        a01 = __hadd2(a01, u2b(q1.x)); a23 = __hadd2(a23, u2b(q1.y));
        a01 = __hadd2(a01, u2b(q2.x)); a23 = __hadd2(a23, u2b(q2.y));
        a01 = __hadd2(a01, u2b(q3.x)); a23 = __hadd2(a23, u2b(q3.y));
    }
    for (; e < p1; ++e) {
        int r = g_srcs[e];
        uint2 q = *(const uint2*)(g_h1b + (size_t)r * 128 + lane * 4);
        a01 = __hadd2(a01, u2b(q.x));
        a23 = __hadd2(a23, u2b(q.y));
    }

    float2 f01 = __bfloat1622float2(a01);
    float2 f23 = __bfloat1622float2(a23);
    float4 bb = ((const float4*)b1)[lane];
    float ax = fmaxf(fmaf(dc, f01.x, bb.x), 0.f);
    float ay = fmaxf(fmaf(dc, f01.y, bb.y), 0.f);
    float az = fmaxf(fmaf(dc, f23.x, bb.z), 0.f);
    float aw = fmaxf(fmaf(dc, f23.y, bb.w), 0.f);

    const float4* w2p = (const float4*)(W2 + lane * 8);
    float4 wA = w2p[0];
    float4 wB = w2p[1];
    float s0 = ax * wA.x + ay * wA.z + az * wB.x + aw * wB.z;
    float s1 = ax * wA.y + ay * wA.w + az * wB.y + aw * wB.w;
#pragma unroll
    for (int off = 16; off > 0; off >>= 1) {
        s0 += __shfl_xor_sync(0xffffffffu, s0, off);
        s1 += __shfl_xor_sync(0xffffffffu, s1, off);
    }
    if (lane == 0) {
        g_h2[warp * 2 + 0] = dc * s0;
        g_h2[warp * 2 + 1] = dc * s1;
    }
}

// ---------- launch 6: layer-2 aggregation + mean-pool partials ------------
__global__ void k_agg2pool(const float* __restrict__ b2,
                           const int* __restrict__ batch) {
    __shared__ float s_sums[NG * NC];
    __shared__ float s_cnt[NG];
    int t = threadIdx.x;
    if (t < NG * NC) s_sums[t] = 0.f;
    if (t < NG) s_cnt[t] = 0.f;
    __syncthreads();

    int i = blockIdx.x * blockDim.x + t;
    if (i < NN) {
        float d = g_dinv[i];
        float a0 = g_h2[i * 2 + 0];
        float a1 = g_h2[i * 2 + 1];
        int p0 = g_ptr[i], p1 = g_ptr[i + 1];
        int e = p0;
        for (; e + 4 <= p1; e += 4) {
            int r0 = g_srcs[e], r1 = g_srcs[e + 1], r2 = g_srcs[e + 2], r3 = g_srcs[e + 3];
            float2 h0 = *(const float2*)(g_h2 + r0 * 2);
            float2 h1 = *(const float2*)(g_h2 + r1 * 2);
            float2 h2 = *(const float2*)(g_h2 + r2 * 2);
            float2 h3 = *(const float2*)(g_h2 + r3 * 2);
            a0 += (h0.x + h1.x) + (h2.x + h3.x);
            a1 += (h0.y + h1.y) + (h2.y + h3.y);
        }
        for (; e < p1; ++e) {
            float2 h = *(const float2*)(g_h2 + g_srcs[e] * 2);
            a0 += h.x; a1 += h.y;
        }
        a0 = fmaf(d, a0, b2[0]);
        a1 = fmaf(d, a1, b2[1]);
        int g = batch[i];
        atomicAdd(&s_sums[g * 2 + 0], a0);
        atomicAdd(&s_sums[g * 2 + 1], a1);
        atomicAdd(&s_cnt[g], 1.f);
    }
    __syncthreads();
    if (t < NG * NC) atomicAdd(&g_sums[t], s_sums[t]);
    if (t < NG) atomicAdd(&g_cnts[t], s_cnt[t]);
}

// ---------- launch 7: log_softmax + state re-zero --------------------------
__global__ void k_finalclean(float* __restrict__ out) {
    int i = blockIdx.x * blockDim.x + threadIdx.x;
    if (i < NN) { g_deg[i] = 0; g_fill[i] = 0; }
    if (blockIdx.x == 0) {
        int t = threadIdx.x;
        if (t < NG) {
            float c = fmaxf(g_cnts[t], 1.f);
            float p0 = g_sums[t * 2 + 0] / c;
            float p1 = g_sums[t * 2 + 1] / c;
            float m = fmaxf(p0, p1);
            float l = m + logf(expf(p0 - m) + expf(p1 - m));
            out[t * 2 + 0] = p0 - l;
            out[t * 2 + 1] = p1 - l;
            g_sums[t * 2 + 0] = 0.f;
            g_sums[t * 2 + 1] = 0.f;
            g_cnts[t] = 0.f;
        }
    }
}

// ---------------- launch --------------------------------------------------
extern "C" void kernel_launch(void* const* d_in, const int* in_sizes, int n_in,
                              void* d_out, int out_size) {
    const float* x     = (const float*)d_in[0];
    const int*   ei    = (const int*)d_in[1];     // int32 (JAX x64 disabled)
    const int*   batch = (const int*)d_in[2];
    const float* W1    = (const float*)d_in[3];
    const float* b1    = (const float*)d_in[4];
    const float* W2    = (const float*)d_in[5];
    const float* b2    = (const float*)d_in[6];
    float* out = (float*)d_out;

    static bool attr_done = false;
    if (!attr_done) {
        cudaFuncSetAttribute(k_gemmfill, cudaFuncAttributeMaxDynamicSharedMemorySize, GSMEM);
        attr_done = true;
    }

    k_histinit<<<HB + 8, 256>>>(ei, W1);
    k_scanA<<<25, 1024>>>();
    k_spineAdd<<<(NN + 1023) / 1024, 1024>>>();
    k_gemmfill<<<GB + FB, 256, GSMEM>>>(x, ei);   // 4th -> ncu slot
    k_agg1h2<<<(NN * 32 + 255) / 256, 256>>>(b1, W2);
    k_agg2pool<<<(NN + 255) / 256, 256>>>(b2, batch);
    k_finalclean<<<(NN + 255) / 256, 256>>>(out);
}